// round 1
// baseline (speedup 1.0000x reference)
#include <cuda_runtime.h>

// Conv2D 3x3 s1 p1 as implicit GEMM (fp32 baseline).
// C[M=256][N=100352] = Wk[M][K=1152] * im2col(x)[K][N], + bias.
// Tiles: BM=128, BN=128, BK=8; 256 threads, 8x8 micro-tile per thread.
// M, N, K all divide the tile sizes exactly -> no edge handling.

namespace {
constexpr int IN_C  = 128;
constexpr int OUT_C = 256;
constexpr int KS    = 3;
constexpr int PAD   = 1;
constexpr int BATCH = 32;
constexpr int H     = 56;
constexpr int W     = 56;
constexpr int HW    = H * W;            // 3136
constexpr int Mdim  = OUT_C;            // 256
constexpr int Ndim  = BATCH * HW;       // 100352
constexpr int Kdim  = IN_C * KS * KS;   // 1152

constexpr int BM = 128;
constexpr int BN = 128;
constexpr int BK = 8;
constexpr int TM = 8;
constexpr int TN = 8;
constexpr int THREADS = (BM / TM) * (BN / TN);  // 256
}  // namespace

__global__ __launch_bounds__(THREADS, 2)
void conv_igemm_fp32(const float* __restrict__ x,
                     const float* __restrict__ Wk,
                     const float* __restrict__ bias,
                     float* __restrict__ out)
{
    __shared__ float As[BK][BM];        // A tile, transposed: As[k][m]
    __shared__ float Bs[BK][BN + 4];    // B tile (im2col gather), padded row

    const int tid = threadIdx.x;
    const int tx  = tid % (BN / TN);    // 0..15 -> N direction
    const int ty  = tid / (BN / TN);    // 0..15 -> M direction

    // ---- per-thread fixed indices for the B (input) gather ----
    const int tcol  = tid & 127;        // column within the 128-wide N tile
    const int krow0 = tid >> 7;         // 0 or 1: base k-row; handles rows {b, b+2, b+4, b+6}
    const int colg  = blockIdx.x * BN + tcol;
    const int n_img = colg / HW;
    const int hw    = colg - n_img * HW;
    const int oh    = hw / W;
    const int ow    = hw - oh * W;
    const float* xn = x + (size_t)n_img * IN_C * HW;

    // ---- per-thread fixed indices for the A (weight) load ----
    const int arow  = tid >> 1;          // 0..127: M row within tile
    const int ahalf = (tid & 1) * 4;     // which half of the 8-wide K slice
    const float* Arow = Wk + (size_t)(blockIdx.y * BM + arow) * Kdim;

    float acc[TM][TN];
    #pragma unroll
    for (int i = 0; i < TM; ++i)
        #pragma unroll
        for (int j = 0; j < TN; ++j)
            acc[i][j] = 0.0f;

    for (int k0 = 0; k0 < Kdim; k0 += BK) {
        // -- load A tile (weights): one float4 per thread, store transposed --
        float4 a4 = *reinterpret_cast<const float4*>(Arow + k0 + ahalf);
        As[ahalf + 0][arow] = a4.x;
        As[ahalf + 1][arow] = a4.y;
        As[ahalf + 2][arow] = a4.z;
        As[ahalf + 3][arow] = a4.w;

        // -- load B tile (im2col gather with zero padding): 4 elems per thread --
        #pragma unroll
        for (int i = 0; i < 4; ++i) {
            const int kl = krow0 + 2 * i;
            const int k  = k0 + kl;
            const int ic = k / 9;
            const int r  = k - ic * 9;
            const int kh = r / 3;
            const int kw = r - kh * 3;
            const int ih = oh + kh - PAD;
            const int iw = ow + kw - PAD;
            float v = 0.0f;
            if ((unsigned)ih < (unsigned)H && (unsigned)iw < (unsigned)W)
                v = xn[(ic * H + ih) * W + iw];
            Bs[kl][tcol] = v;
        }
        __syncthreads();

        // -- 8x8 register micro-tile over the 8-deep K slice --
        #pragma unroll
        for (int kk = 0; kk < BK; ++kk) {
            float ra[TM], rb[TN];
            *reinterpret_cast<float4*>(&ra[0]) =
                *reinterpret_cast<const float4*>(&As[kk][ty * TM]);
            *reinterpret_cast<float4*>(&ra[4]) =
                *reinterpret_cast<const float4*>(&As[kk][ty * TM + 4]);
            *reinterpret_cast<float4*>(&rb[0]) =
                *reinterpret_cast<const float4*>(&Bs[kk][tx * TN]);
            *reinterpret_cast<float4*>(&rb[4]) =
                *reinterpret_cast<const float4*>(&Bs[kk][tx * TN + 4]);
            #pragma unroll
            for (int i = 0; i < TM; ++i)
                #pragma unroll
                for (int j = 0; j < TN; ++j)
                    acc[i][j] += ra[i] * rb[j];
        }
        __syncthreads();
    }

    // ---- epilogue: bias add + coalesced float4 stores ----
    const int c_row0 = blockIdx.y * BM + ty * TM;       // output channel base
    const int c_col0 = blockIdx.x * BN + tx * TN;       // flattened (n,h,w) base
    const int n2  = c_col0 / HW;                         // col0 % 8 == 0 and HW % 8 == 0
    const int hw2 = c_col0 - n2 * HW;                    // -> all 8 cols share n2

    #pragma unroll
    for (int i = 0; i < TM; ++i) {
        const int oc = c_row0 + i;
        const float bv = bias[oc];
        float* dst = out + (size_t)(n2 * OUT_C + oc) * HW + hw2;
        float4 o0 = make_float4(acc[i][0] + bv, acc[i][1] + bv,
                                acc[i][2] + bv, acc[i][3] + bv);
        float4 o1 = make_float4(acc[i][4] + bv, acc[i][5] + bv,
                                acc[i][6] + bv, acc[i][7] + bv);
        *reinterpret_cast<float4*>(dst)     = o0;
        *reinterpret_cast<float4*>(dst + 4) = o1;
    }
}

extern "C" void kernel_launch(void* const* d_in, const int* in_sizes, int n_in,
                              void* d_out, int out_size) {
    const float* x    = (const float*)d_in[0];
    const float* Wk   = (const float*)d_in[1];
    const float* bias = (const float*)d_in[2];
    float* out        = (float*)d_out;

    dim3 grid(Ndim / BN, Mdim / BM);   // (784, 2)
    conv_igemm_fp32<<<grid, THREADS>>>(x, Wk, bias, out);
}

// round 3
// speedup vs baseline: 2.5874x; 2.5874x over previous
#include <cuda_runtime.h>
#include <cuda_bf16.h>
#include <cstdint>

// Conv2D 3x3 s1 p1 -> implicit GEMM via mma.sync bf16 (m16n8k16) with
// 3-term hi/lo split (hh + hl + lh) for fp32-grade accuracy.
//  D[256][100352] = Wk[256][1152] @ im2col(x)[1152][100352] + bias
// tcgen05 is unavailable (harness compiles at compute_103, no 'a'), so we use
// the arch-portable HMMA path: ldmatrix + mma.sync, fused im2col gather
// (x fits in L2, 9x reuse is L2-served), double-buffered SMEM.

namespace {
constexpr int IN_C = 128, OUT_C = 256, H = 56, W = 56, BATCH = 32;
constexpr int HW   = H * W;            // 3136
constexpr int Ndim = BATCH * HW;       // 100352
constexpr int Kdim = IN_C * 9;         // 1152

constexpr int BM = 128, BN = 128, BK = 32;
constexpr int NCH = Kdim / BK;         // 36 k-chunks

constexpr int AS_STRIDE = 40;          // bf16 elems per A smem row (pad 32->40)
constexpr int BS_STRIDE = 136;         // bf16 elems per B smem row (pad 128->136)
constexpr int AS_BYTES  = BM * AS_STRIDE * 2;   // 10240
constexpr int BS_BYTES  = BK * BS_STRIDE * 2;   // 8704

constexpr int OFF_AHI = 0;
constexpr int OFF_ALO = AS_BYTES;               // 10240
constexpr int OFF_BHI = 2 * AS_BYTES;           // 20480
constexpr int OFF_BLO = 2 * AS_BYTES + BS_BYTES;// 29184
constexpr int STAGE   = 2 * AS_BYTES + 2 * BS_BYTES;  // 37888
constexpr int SMEM_TOTAL = 2 * STAGE;                 // 75776
}  // namespace

// device scratch (allocation-free rule): weights as bf16 hi/lo, row-major [m][k]
__device__ __nv_bfloat16 g_Ahi[OUT_C * Kdim];
__device__ __nv_bfloat16 g_Alo[OUT_C * Kdim];

// ---------------- helpers ----------------
__device__ __forceinline__ uint32_t smem_u32(const void* p) {
    uint32_t a;
    asm("{ .reg .u64 t; cvta.to.shared.u64 t, %1; cvt.u32.u64 %0, t; }" : "=r"(a) : "l"(p));
    return a;
}
__device__ __forceinline__ void ldsm4(uint32_t r[4], uint32_t addr) {
    asm volatile("ldmatrix.sync.aligned.m8n8.x4.shared.b16 {%0,%1,%2,%3}, [%4];"
                 : "=r"(r[0]), "=r"(r[1]), "=r"(r[2]), "=r"(r[3]) : "r"(addr));
}
__device__ __forceinline__ void ldsm4t(uint32_t r[4], uint32_t addr) {
    asm volatile("ldmatrix.sync.aligned.m8n8.x4.trans.shared.b16 {%0,%1,%2,%3}, [%4];"
                 : "=r"(r[0]), "=r"(r[1]), "=r"(r[2]), "=r"(r[3]) : "r"(addr));
}
__device__ __forceinline__ void mma_bf16(float acc[4], const uint32_t a[4],
                                         uint32_t b0, uint32_t b1) {
    asm volatile(
        "mma.sync.aligned.m16n8k16.row.col.f32.bf16.bf16.f32 "
        "{%0,%1,%2,%3}, {%4,%5,%6,%7}, {%8,%9}, {%0,%1,%2,%3};"
        : "+f"(acc[0]), "+f"(acc[1]), "+f"(acc[2]), "+f"(acc[3])
        : "r"(a[0]), "r"(a[1]), "r"(a[2]), "r"(a[3]), "r"(b0), "r"(b1));
}
__device__ __forceinline__ uint32_t pack2(__nv_bfloat16 a, __nv_bfloat16 b) {
    __nv_bfloat162 t(a, b);
    return *reinterpret_cast<uint32_t*>(&t);
}

// ---------------- prep: weights fp32 -> bf16 hi/lo ----------------
__global__ void prep_weights(const float* __restrict__ Wk) {
    int i = blockIdx.x * blockDim.x + threadIdx.x;   // 36864 threads, 8 elems each
    if (i >= OUT_C * Kdim / 8) return;
    const float4* s = reinterpret_cast<const float4*>(Wk) + (size_t)i * 2;
    float4 v0 = s[0], v1 = s[1];
    float vv[8] = {v0.x, v0.y, v0.z, v0.w, v1.x, v1.y, v1.z, v1.w};
    uint32_t hi[4], lo[4];
    #pragma unroll
    for (int p = 0; p < 4; ++p) {
        float a = vv[2 * p], b = vv[2 * p + 1];
        __nv_bfloat16 h0 = __float2bfloat16(a);
        __nv_bfloat16 h1 = __float2bfloat16(b);
        __nv_bfloat16 l0 = __float2bfloat16(a - __bfloat162float(h0));
        __nv_bfloat16 l1 = __float2bfloat16(b - __bfloat162float(h1));
        hi[p] = pack2(h0, h1);
        lo[p] = pack2(l0, l1);
    }
    reinterpret_cast<uint4*>(g_Ahi)[i] = make_uint4(hi[0], hi[1], hi[2], hi[3]);
    reinterpret_cast<uint4*>(g_Alo)[i] = make_uint4(lo[0], lo[1], lo[2], lo[3]);
}

// ---------------- GEMM ----------------
__global__ __launch_bounds__(256)
void conv_mma(const float* __restrict__ x, const float* __restrict__ bias,
              float* __restrict__ out)
{
    extern __shared__ char smem[];
    const uint32_t sb = smem_u32(smem);
    const int tid = threadIdx.x, lane = tid & 31, wp = tid >> 5;
    const int warp_m = wp >> 2, warp_n = wp & 3;          // 2 x 4 warp grid
    const int mblk = blockIdx.y, nblk = blockIdx.x;

    // ---- fixed geometry for the fused im2col gather (4 columns/thread) ----
    const int krow0 = wp * 4;                             // this warp's 4 k-rows
    const float* xbase[4];
    int oh[4], ow[4];
    #pragma unroll
    for (int j = 0; j < 4; ++j) {
        int g  = nblk * BN + lane + 32 * j;
        int ni = g / HW;
        int hw = g - ni * HW;
        oh[j] = hw / W;
        ow[j] = hw - oh[j] * W;
        xbase[j] = x + (size_t)ni * IN_C * HW;
    }

    // ---- fixed indices for A (weights, prepacked bf16) loads ----
    const int arow0 = tid >> 2;        // 0..63 ; slot1 = +64
    const int aq    = tid & 3;
    const __nv_bfloat16* Ahg = g_Ahi + (size_t)(mblk * BM + arow0) * Kdim + aq * 8;
    const __nv_bfloat16* Alg = g_Alo + (size_t)(mblk * BM + arow0) * Kdim + aq * 8;

    float acc[4][4][4];
    #pragma unroll
    for (int a = 0; a < 4; ++a)
        #pragma unroll
        for (int b = 0; b < 4; ++b)
            #pragma unroll
            for (int c = 0; c < 4; ++c) acc[a][b][c] = 0.f;

    // ldmatrix per-lane byte offsets
    const uint32_t a_lane = ((warp_m * 64 + (lane & 15)) * AS_STRIDE + (lane >> 4) * 8) * 2;
    const uint32_t b_lane = ((lane & 15) * BS_STRIDE + warp_n * 32 + (lane >> 4) * 8) * 2;

    // pipeline registers
    float bvals[16];
    uint4 avh[2], avl[2];

    auto ldg_chunk = [&](int c) {
        #pragma unroll
        for (int s = 0; s < 2; ++s) {
            avh[s] = *reinterpret_cast<const uint4*>(Ahg + (size_t)s * 64 * Kdim + c * BK);
            avl[s] = *reinterpret_cast<const uint4*>(Alg + (size_t)s * 64 * Kdim + c * BK);
        }
        #pragma unroll
        for (int i = 0; i < 4; ++i) {
            int k  = c * BK + krow0 + i;
            int ic = k / 9;
            int r9 = k - ic * 9;
            int kh = r9 / 3, kw = r9 - kh * 3;
            #pragma unroll
            for (int j = 0; j < 4; ++j) {
                int ih = oh[j] + kh - 1, iw = ow[j] + kw - 1;
                float v = 0.f;
                if ((unsigned)ih < (unsigned)H && (unsigned)iw < (unsigned)W)
                    v = __ldg(xbase[j] + (ic * H + ih) * W + iw);
                bvals[i * 4 + j] = v;
            }
        }
    };

    auto sts_chunk = [&](int buf) {
        char* st = smem + buf * STAGE;
        #pragma unroll
        for (int s = 0; s < 2; ++s) {
            int row = arow0 + s * 64;
            *reinterpret_cast<uint4*>(st + OFF_AHI + row * 80 + aq * 16) = avh[s];
            *reinterpret_cast<uint4*>(st + OFF_ALO + row * 80 + aq * 16) = avl[s];
        }
        #pragma unroll
        for (int i = 0; i < 4; ++i) {
            int k = krow0 + i;
            #pragma unroll
            for (int j = 0; j < 4; ++j) {
                int n = lane + 32 * j;
                float v = bvals[i * 4 + j];
                __nv_bfloat16 h = __float2bfloat16(v);
                __nv_bfloat16 l = __float2bfloat16(v - __bfloat162float(h));
                *reinterpret_cast<__nv_bfloat16*>(st + OFF_BHI + k * 272 + n * 2) = h;
                *reinterpret_cast<__nv_bfloat16*>(st + OFF_BLO + k * 272 + n * 2) = l;
            }
        }
    };

    auto compute = [&](int buf) {
        const uint32_t base = sb + buf * STAGE;
        #pragma unroll
        for (int ks = 0; ks < 2; ++ks) {
            uint32_t Ah[4][4], Al[4][4], Bh[2][4], Bl[2][4];
            #pragma unroll
            for (int mt = 0; mt < 4; ++mt) {
                uint32_t ad = base + OFF_AHI + a_lane + mt * (16 * 80) + ks * 32;
                ldsm4(Ah[mt], ad);
                ldsm4(Al[mt], ad + (OFF_ALO - OFF_AHI));
            }
            #pragma unroll
            for (int jh = 0; jh < 2; ++jh) {
                uint32_t bd = base + OFF_BHI + b_lane + ks * (16 * 272) + jh * 32;
                ldsm4t(Bh[jh], bd);
                ldsm4t(Bl[jh], bd + (OFF_BLO - OFF_BHI));
            }
            #pragma unroll
            for (int mt = 0; mt < 4; ++mt)
                #pragma unroll
                for (int nt = 0; nt < 4; ++nt) {
                    uint32_t bh0 = Bh[nt >> 1][(nt & 1) * 2];
                    uint32_t bh1 = Bh[nt >> 1][(nt & 1) * 2 + 1];
                    uint32_t bl0 = Bl[nt >> 1][(nt & 1) * 2];
                    uint32_t bl1 = Bl[nt >> 1][(nt & 1) * 2 + 1];
                    mma_bf16(acc[mt][nt], Ah[mt], bh0, bh1);   // hh
                    mma_bf16(acc[mt][nt], Ah[mt], bl0, bl1);   // hl
                    mma_bf16(acc[mt][nt], Al[mt], bh0, bh1);   // lh
                }
        }
    };

    // ---- mainloop: double-buffered SMEM, register-staged loads ----
    ldg_chunk(0);
    sts_chunk(0);
    __syncthreads();
    for (int c = 0; c < NCH; ++c) {
        if (c + 1 < NCH) ldg_chunk(c + 1);
        compute(c & 1);
        if (c + 1 < NCH) sts_chunk((c + 1) & 1);
        __syncthreads();
    }

    // ---- epilogue: bias + direct stores ----
    #pragma unroll
    for (int mt = 0; mt < 4; ++mt) {
        int oc0 = mblk * BM + warp_m * 64 + mt * 16 + (lane >> 2);
        float b0 = bias[oc0], b1 = bias[oc0 + 8];
        #pragma unroll
        for (int nt = 0; nt < 4; ++nt) {
            int g  = nblk * BN + warp_n * 32 + nt * 8 + (lane & 3) * 2;
            int ni = g / HW;
            int hw = g - ni * HW;
            float2 v0 = make_float2(acc[mt][nt][0] + b0, acc[mt][nt][1] + b0);
            float2 v1 = make_float2(acc[mt][nt][2] + b1, acc[mt][nt][3] + b1);
            *reinterpret_cast<float2*>(out + ((size_t)ni * OUT_C + oc0) * HW + hw)       = v0;
            *reinterpret_cast<float2*>(out + ((size_t)ni * OUT_C + oc0 + 8) * HW + hw)   = v1;
        }
    }
}

// ---------------- launch ----------------
extern "C" void kernel_launch(void* const* d_in, const int* in_sizes, int n_in,
                              void* d_out, int out_size) {
    const float* x    = (const float*)d_in[0];
    const float* Wk   = (const float*)d_in[1];
    const float* bias = (const float*)d_in[2];
    float* out        = (float*)d_out;

    cudaFuncSetAttribute(conv_mma, cudaFuncAttributeMaxDynamicSharedMemorySize, SMEM_TOTAL);

    prep_weights<<<(OUT_C * Kdim / 8 + 255) / 256, 256>>>(Wk);
    conv_mma<<<dim3(Ndim / BN, OUT_C / BM), 256, SMEM_TOTAL>>>(x, bias, out);
}

// round 4
// speedup vs baseline: 3.3340x; 1.2886x over previous
#include <cuda_runtime.h>
#include <cuda_bf16.h>
#include <cstdint>

// Conv2D 3x3 s1 p1 -> implicit GEMM, mma.sync bf16 m16n8k16, 3-term hi/lo
// (hh + hl + lh). R4: im2col is MATERIALIZED by a prep kernel (k-reordered so
// one chunk = one spatial offset => fully vectorized), stored in gmem as
// byte-exact SMEM tile images. GEMM mainloop is then pure:
// cp.async.bulk (linear memcpy) -> mbarrier -> ldmatrix -> HMMA.
// No __syncthreads in the mainloop; 2 CTAs/SM.

namespace {
constexpr int IN_C = 128, OUT_C = 256, H = 56, W = 56, BATCH = 32;
constexpr int HW   = H * W;            // 3136
constexpr int Ndim = BATCH * HW;       // 100352
constexpr int Kdim = IN_C * 9;         // 1152

constexpr int BM = 128, BN = 128, BK = 32;
constexpr int NCH  = Kdim / BK;        // 36 chunks; chunk c: r=c>>2, ic0=(c&3)*32
constexpr int MBLK = OUT_C / BM;       // 2
constexpr int NT   = Ndim / BN;        // 784

// SMEM tile images (same padding as gmem images -> bulk copy is linear)
constexpr int A_HALF = BM * 80;        // [128 m][32 k] bf16, 80B rows (pad)
constexpr int A_CH   = 2 * A_HALF;     // hi + lo = 20480
constexpr int B_HALF = BK * 272;       // [32 k][128 n] bf16, 272B rows (pad)
constexpr int B_CH   = 2 * B_HALF;     // 17408
constexpr int STAGE  = A_CH + B_CH;    // 37888
constexpr int OFF_A  = 0;
constexpr int OFF_B  = A_CH;
constexpr int SM_BAR = 2 * STAGE;      // 75776
constexpr int SMEM_TOTAL = SM_BAR + 64;
}  // namespace

// device scratch (allocation-free rule)
__device__ __align__(16) unsigned char g_A[(size_t)MBLK * NCH * A_CH];   // 1.4MB
__device__ __align__(16) unsigned char g_B[(size_t)NT * NCH * B_CH];     // 491MB

// ---------------- helpers ----------------
__device__ __forceinline__ uint32_t smem_u32(const void* p) {
    uint32_t a;
    asm("{ .reg .u64 t; cvta.to.shared.u64 t, %1; cvt.u32.u64 %0, t; }" : "=r"(a) : "l"(p));
    return a;
}
__device__ __forceinline__ void ldsm4(uint32_t r[4], uint32_t addr) {
    asm volatile("ldmatrix.sync.aligned.m8n8.x4.shared.b16 {%0,%1,%2,%3}, [%4];"
                 : "=r"(r[0]), "=r"(r[1]), "=r"(r[2]), "=r"(r[3]) : "r"(addr));
}
__device__ __forceinline__ void ldsm4t(uint32_t r[4], uint32_t addr) {
    asm volatile("ldmatrix.sync.aligned.m8n8.x4.trans.shared.b16 {%0,%1,%2,%3}, [%4];"
                 : "=r"(r[0]), "=r"(r[1]), "=r"(r[2]), "=r"(r[3]) : "r"(addr));
}
__device__ __forceinline__ void mma_bf16(float acc[4], const uint32_t a[4],
                                         uint32_t b0, uint32_t b1) {
    asm volatile(
        "mma.sync.aligned.m16n8k16.row.col.f32.bf16.bf16.f32 "
        "{%0,%1,%2,%3}, {%4,%5,%6,%7}, {%8,%9}, {%0,%1,%2,%3};"
        : "+f"(acc[0]), "+f"(acc[1]), "+f"(acc[2]), "+f"(acc[3])
        : "r"(a[0]), "r"(a[1]), "r"(a[2]), "r"(a[3]), "r"(b0), "r"(b1));
}
__device__ __forceinline__ uint32_t pack2(__nv_bfloat16 a, __nv_bfloat16 b) {
    __nv_bfloat162 t(a, b);
    return *reinterpret_cast<uint32_t*>(&t);
}
#define MBAR_INIT(a, n)   asm volatile("mbarrier.init.shared.b64 [%0], %1;" :: "r"(a), "r"(n) : "memory")
#define MBAR_EXPECT(a, b) asm volatile("mbarrier.arrive.expect_tx.shared.b64 _, [%0], %1;" :: "r"(a), "r"(b) : "memory")
#define MBAR_ARRIVE(a)    asm volatile("mbarrier.arrive.shared.b64 _, [%0];" :: "r"(a) : "memory")
#define MBAR_INVAL(a)     asm volatile("mbarrier.inval.shared.b64 [%0];" :: "r"(a) : "memory")
__device__ __forceinline__ void mbar_wait(uint32_t mbar, uint32_t parity) {
    asm volatile(
        "{\n\t.reg .pred P;\n"
        "WL_%=:\n\t"
        "mbarrier.try_wait.parity.acquire.cta.shared::cta.b64 P, [%0], %1, 0x989680;\n\t"
        "@P bra.uni WD_%=;\n\t"
        "bra.uni WL_%=;\n"
        "WD_%=:\n\t}"
        :: "r"(mbar), "r"(parity) : "memory");
}
__device__ __forceinline__ void bulk_g2s(uint32_t dst, const void* src, uint32_t bytes, uint32_t mbar) {
    asm volatile(
        "cp.async.bulk.shared::cluster.global.mbarrier::complete_tx::bytes [%0], [%1], %2, [%3];"
        :: "r"(dst), "l"(src), "r"(bytes), "r"(mbar) : "memory");
}
__device__ __forceinline__ void split_bf16(float v, __nv_bfloat16& h, __nv_bfloat16& l) {
    h = __float2bfloat16(v);
    l = __float2bfloat16(v - __bfloat162float(h));
}

// ---------------- prep: weights -> k-reordered SMEM-image bf16 hi/lo -------
__global__ void prep_weights(const float* __restrict__ Wk) {
    int idx = blockIdx.x * blockDim.x + threadIdx.x;   // 256m * 36c * 4grp = 36864
    if (idx >= OUT_C * NCH * 4) return;
    int kkg = idx & 3;
    int c   = (idx >> 2) % NCH;
    int m   = idx / (4 * NCH);
    int r   = c >> 2;
    int icb = (c & 3) * 32 + kkg * 8;

    const float* src = Wk + (size_t)m * Kdim + r;      // orig k = ic*9 + r
    uint32_t hi[4], lo[4];
    #pragma unroll
    for (int p = 0; p < 4; ++p) {
        __nv_bfloat16 h0, l0, h1, l1;
        split_bf16(src[(icb + 2 * p) * 9], h0, l0);
        split_bf16(src[(icb + 2 * p + 1) * 9], h1, l1);
        hi[p] = pack2(h0, h1);
        lo[p] = pack2(l0, l1);
    }
    size_t base = ((size_t)(m >> 7) * NCH + c) * A_CH + (size_t)(m & 127) * 80 + kkg * 16;
    *reinterpret_cast<uint4*>(g_A + base)          = make_uint4(hi[0], hi[1], hi[2], hi[3]);
    *reinterpret_cast<uint4*>(g_A + base + A_HALF) = make_uint4(lo[0], lo[1], lo[2], lo[3]);
}

// ---------------- prep: im2col(x) -> SMEM-image bf16 hi/lo -----------------
__global__ __launch_bounds__(256)
void prep_im2col(const float* __restrict__ x) {
    const int c = blockIdx.x;          // chunk: one (kh,kw), 32 ic
    const int t = blockIdx.y;          // n tile
    const int tid = threadIdx.x;
    const int g  = tid & 15;           // n group of 8
    const int kk = tid >> 4;           // rows kk, kk+16

    const int r  = c >> 2;
    const int kh = r / 3, kw = r - kh * 3;
    const int icb = (c & 3) * 32;

    const int n0  = t * 128 + g * 8;   // 8-aligned => one image, one row
    const int ni  = n0 / HW;
    const int hw0 = n0 - ni * HW;
    const int oh  = hw0 / W;
    const int ow0 = hw0 - oh * W;
    const int ih  = oh + kh - 1;
    const bool rv = (unsigned)ih < (unsigned)H;

    const size_t tb = ((size_t)t * NCH + c) * B_CH;

    #pragma unroll
    for (int s = 0; s < 2; ++s) {
        const int row = kk + s * 16;
        const int ic  = icb + row;
        const float* src = x + (((size_t)ni * IN_C + ic) * H + ih) * W;
        uint32_t hi[4], lo[4];
        #pragma unroll
        for (int p = 0; p < 4; ++p) {
            float v0 = 0.f, v1 = 0.f;
            int iw0 = ow0 + kw - 1 + 2 * p;
            if (rv) {
                if ((unsigned)iw0 < (unsigned)W)       v0 = __ldg(src + iw0);
                if ((unsigned)(iw0 + 1) < (unsigned)W) v1 = __ldg(src + iw0 + 1);
            }
            __nv_bfloat16 h0, l0, h1, l1;
            split_bf16(v0, h0, l0);
            split_bf16(v1, h1, l1);
            hi[p] = pack2(h0, h1);
            lo[p] = pack2(l0, l1);
        }
        size_t o = tb + (size_t)row * 272 + g * 16;
        *reinterpret_cast<uint4*>(g_B + o)          = make_uint4(hi[0], hi[1], hi[2], hi[3]);
        *reinterpret_cast<uint4*>(g_B + o + B_HALF) = make_uint4(lo[0], lo[1], lo[2], lo[3]);
    }
}

// ---------------- GEMM: pure HMMA with bulk-copy pipeline ------------------
__global__ __launch_bounds__(256, 2)
void conv_mma2(const float* __restrict__ bias, float* __restrict__ out)
{
    extern __shared__ char smem[];
    const uint32_t sb = smem_u32(smem);
    const int tid = threadIdx.x, lane = tid & 31, wp = tid >> 5;
    const int warp_m = wp >> 2, warp_n = wp & 3;
    const int t = blockIdx.x, mblk = blockIdx.y;

    const uint32_t full[2] = {sb + SM_BAR, sb + SM_BAR + 8};
    const uint32_t emp[2]  = {sb + SM_BAR + 16, sb + SM_BAR + 24};
    if (tid == 0) {
        MBAR_INIT(full[0], 1); MBAR_INIT(full[1], 1);
        MBAR_INIT(emp[0], 256); MBAR_INIT(emp[1], 256);
    }
    __syncthreads();

    const unsigned char* gA = g_A + (size_t)mblk * NCH * A_CH;
    const unsigned char* gB = g_B + (size_t)t * NCH * B_CH;

    auto load = [&](int c, int b) {
        uint32_t st = sb + b * STAGE;
        MBAR_EXPECT(full[b], STAGE);
        bulk_g2s(st + OFF_A, gA + (size_t)c * A_CH, A_CH, full[b]);
        bulk_g2s(st + OFF_B, gB + (size_t)c * B_CH, B_CH, full[b]);
    };
    if (tid == 0) { load(0, 0); load(1, 1); }

    float acc[4][4][4];
    #pragma unroll
    for (int a = 0; a < 4; ++a)
        #pragma unroll
        for (int b = 0; b < 4; ++b)
            #pragma unroll
            for (int cc = 0; cc < 4; ++cc) acc[a][b][cc] = 0.f;

    const uint32_t a_lane = (warp_m * 64 + (lane & 15)) * 80 + (lane >> 4) * 16;
    const uint32_t b_lane = (lane & 15) * 272 + warp_n * 64 + (lane >> 4) * 16;

    int fp[2] = {0, 0}, ep[2] = {0, 0};
    for (int c = 0; c < NCH; ++c) {
        const int b = c & 1;
        mbar_wait(full[b], fp[b]); fp[b] ^= 1;

        const uint32_t ab = sb + b * STAGE + OFF_A + a_lane;
        const uint32_t bb = sb + b * STAGE + OFF_B + b_lane;
        #pragma unroll
        for (int ks = 0; ks < 2; ++ks) {
            uint32_t Bh[2][4], Bl[2][4];
            #pragma unroll
            for (int jh = 0; jh < 2; ++jh) {
                ldsm4t(Bh[jh], bb + ks * 4352 + jh * 32);
                ldsm4t(Bl[jh], bb + ks * 4352 + jh * 32 + B_HALF);
            }
            #pragma unroll
            for (int mt = 0; mt < 4; ++mt) {
                uint32_t Ah[4], Al[4];
                ldsm4(Ah, ab + mt * 1280 + ks * 32);
                ldsm4(Al, ab + mt * 1280 + ks * 32 + A_HALF);
                #pragma unroll
                for (int nt = 0; nt < 4; ++nt) {
                    uint32_t bh0 = Bh[nt >> 1][(nt & 1) * 2];
                    uint32_t bh1 = Bh[nt >> 1][(nt & 1) * 2 + 1];
                    uint32_t bl0 = Bl[nt >> 1][(nt & 1) * 2];
                    uint32_t bl1 = Bl[nt >> 1][(nt & 1) * 2 + 1];
                    mma_bf16(acc[mt][nt], Ah, bh0, bh1);   // hh
                    mma_bf16(acc[mt][nt], Ah, bl0, bl1);   // hl
                    mma_bf16(acc[mt][nt], Al, bh0, bh1);   // lh
                }
            }
        }
        MBAR_ARRIVE(emp[b]);
        if (tid == 0 && c + 2 < NCH) {
            mbar_wait(emp[b], ep[b]); ep[b] ^= 1;
            load(c + 2, b);
        }
    }

    // ---- epilogue: bias + direct stores (layout proven in R3) ----
    #pragma unroll
    for (int mt = 0; mt < 4; ++mt) {
        int oc0 = mblk * BM + warp_m * 64 + mt * 16 + (lane >> 2);
        float b0 = bias[oc0], b1 = bias[oc0 + 8];
        #pragma unroll
        for (int nt = 0; nt < 4; ++nt) {
            int g  = t * BN + warp_n * 32 + nt * 8 + (lane & 3) * 2;
            int ni = g / HW;
            int hw = g - ni * HW;
            float2 v0 = make_float2(acc[mt][nt][0] + b0, acc[mt][nt][1] + b0);
            float2 v1 = make_float2(acc[mt][nt][2] + b1, acc[mt][nt][3] + b1);
            *reinterpret_cast<float2*>(out + ((size_t)ni * OUT_C + oc0) * HW + hw)     = v0;
            *reinterpret_cast<float2*>(out + ((size_t)ni * OUT_C + oc0 + 8) * HW + hw) = v1;
        }
    }

    __syncthreads();
    if (tid == 0) {
        MBAR_INVAL(full[0]); MBAR_INVAL(full[1]);
        MBAR_INVAL(emp[0]);  MBAR_INVAL(emp[1]);
    }
}

// ---------------- launch ----------------
extern "C" void kernel_launch(void* const* d_in, const int* in_sizes, int n_in,
                              void* d_out, int out_size) {
    const float* x    = (const float*)d_in[0];
    const float* Wk   = (const float*)d_in[1];
    const float* bias = (const float*)d_in[2];
    float* out        = (float*)d_out;

    cudaFuncSetAttribute(conv_mma2, cudaFuncAttributeMaxDynamicSharedMemorySize, SMEM_TOTAL);

    prep_weights<<<(OUT_C * NCH * 4 + 255) / 256, 256>>>(Wk);
    prep_im2col<<<dim3(NCH, NT), 256>>>(x);
    conv_mma2<<<dim3(NT, MBLK), 256, SMEM_TOTAL>>>(bias, out);
}